// round 3
// baseline (speedup 1.0000x reference)
#include <cuda_runtime.h>
#include <cuda_fp16.h>
#include <cstdint>

// Problem constants
#define BDIM 8192
#define DDIM 1024
#define UDIM 1024
#define EDIM 16

// Tiling
#define BM 64          // rows per CTA
#define BN 256         // n-chunk per GEMM pass
#define KC 32          // k stage depth
#define NTHREADS 512   // 16 warps: 4 (m) x 4 (n); warp tile 16 x 64

#define AS_STRIDE 36   // As: [BM][KC+4] tf32 words
#define WS_STRIDE 264  // Ws: [KC][BN+8] tf32 words
#define EB_STRIDE 516  // exp buffer row stride in half2 (512 + 4 pad -> conflict-free)
#define NSEC 16        // 64-col sections per row

// SMEM layout (in floats)
#define SMEM_EBUF_OFF 0                                  // [BM][EB_STRIDE] half2 = BM*EB_STRIDE floats
#define SMEM_LMAX_OFF (BM * EB_STRIDE)                   // [BM][NSEC] f32
#define SMEM_LSUM_OFF (SMEM_LMAX_OFF + BM * NSEC)
#define SMEM_AS_OFF   (SMEM_LSUM_OFF + BM * NSEC)
#define SMEM_WS_OFF   (SMEM_AS_OFF + BM * AS_STRIDE)
#define SMEM_FLOATS   (SMEM_WS_OFF + KC * WS_STRIDE)     // 45824 floats = 183296 B

__device__ __forceinline__ uint32_t f2tf32(float x) {
    uint32_t r;
    asm("cvt.rna.tf32.f32 %0, %1;" : "=r"(r) : "f"(x));
    return r;
}

__device__ __forceinline__ void mma_tf32(float c[4],
                                         uint32_t a0, uint32_t a1, uint32_t a2, uint32_t a3,
                                         uint32_t b0, uint32_t b1) {
    asm volatile(
        "mma.sync.aligned.m16n8k8.row.col.f32.tf32.tf32.f32 "
        "{%0,%1,%2,%3}, {%4,%5,%6,%7}, {%8,%9}, {%0,%1,%2,%3};"
        : "+f"(c[0]), "+f"(c[1]), "+f"(c[2]), "+f"(c[3])
        : "r"(a0), "r"(a1), "r"(a2), "r"(a3), "r"(b0), "r"(b1));
}

__global__ __launch_bounds__(NTHREADS, 1)
void fused_proj_softmax_kernel(const float* __restrict__ X,
                               const float* __restrict__ TP,
                               const float* __restrict__ W,
                               const float* __restrict__ bias,
                               float* __restrict__ out) {
    extern __shared__ float smem[];
    __half2*  ebuf = reinterpret_cast<__half2*>(smem + SMEM_EBUF_OFF);  // [BM][EB_STRIDE]
    float*    lmax = smem + SMEM_LMAX_OFF;                               // [BM][NSEC]
    float*    lsum = smem + SMEM_LSUM_OFF;                               // [BM][NSEC]
    uint32_t* As   = reinterpret_cast<uint32_t*>(smem + SMEM_AS_OFF);    // [BM][AS_STRIDE]
    uint32_t* Ws   = reinterpret_cast<uint32_t*>(smem + SMEM_WS_OFF);    // [KC][WS_STRIDE]

    const int tid  = threadIdx.x;
    const int warp = tid >> 5;
    const int lane = tid & 31;
    const int row0 = blockIdx.x * BM;
    const int wm   = warp >> 2;   // 0..3  (16 rows each)
    const int wn   = warp & 3;    // 0..3  (64 cols each)
    const int gid  = lane >> 2;   // 0..7
    const int tig  = lane & 3;    // 0..3

    // A staging: all 512 threads, one float4 each: row a_r, float4 index a_kq
    const int a_r  = tid >> 3;    // 0..63
    const int a_kq = tid & 7;     // 0..7
    // B staging: row b_kk, 4 float4 at b_c4 + 16*j
    const int b_kk = tid >> 4;    // 0..31
    const int b_c4 = tid & 15;    // 0..15

    for (int e = 0; e < EDIM; ++e) {
        const float* We = W + (size_t)e * DDIM * UDIM;

        for (int n0 = 0; n0 < UDIM; n0 += BN) {
            float acc[8][4];
#pragma unroll
            for (int nf = 0; nf < 8; ++nf)
#pragma unroll
                for (int i = 0; i < 4; ++i) acc[nf][i] = 0.f;

            // ---- prefetch stage k0 = 0 into registers ----
            float4 aReg = *reinterpret_cast<const float4*>(
                X + (size_t)(row0 + a_r) * DDIM + 4 * a_kq);
            float4 bReg[4];
            {
                const float* src = We + (size_t)b_kk * UDIM + n0;
#pragma unroll
                for (int j = 0; j < 4; ++j)
                    bReg[j] = *reinterpret_cast<const float4*>(src + 4 * (b_c4 + 16 * j));
            }

            for (int k0 = 0; k0 < DDIM; k0 += KC) {
                // ---- store prefetched regs to SMEM (tf32-rounded) ----
                {
                    uint4 u;
                    u.x = f2tf32(aReg.x); u.y = f2tf32(aReg.y);
                    u.z = f2tf32(aReg.z); u.w = f2tf32(aReg.w);
                    *reinterpret_cast<uint4*>(As + a_r * AS_STRIDE + 4 * a_kq) = u;
                }
                {
                    uint32_t* dstrow = Ws + b_kk * WS_STRIDE;
#pragma unroll
                    for (int j = 0; j < 4; ++j) {
                        uint4 u;
                        u.x = f2tf32(bReg[j].x); u.y = f2tf32(bReg[j].y);
                        u.z = f2tf32(bReg[j].z); u.w = f2tf32(bReg[j].w);
                        *reinterpret_cast<uint4*>(dstrow + 4 * (b_c4 + 16 * j)) = u;
                    }
                }
                __syncthreads();

                // ---- prefetch next stage (overlaps MMAs below) ----
                const int kn = k0 + KC;
                if (kn < DDIM) {
                    aReg = *reinterpret_cast<const float4*>(
                        X + (size_t)(row0 + a_r) * DDIM + kn + 4 * a_kq);
                    const float* src = We + (size_t)(kn + b_kk) * UDIM + n0;
#pragma unroll
                    for (int j = 0; j < 4; ++j)
                        bReg[j] = *reinterpret_cast<const float4*>(src + 4 * (b_c4 + 16 * j));
                }

                // ---- MMAs on current stage: warp tile 16 x 64 ----
#pragma unroll
                for (int ks = 0; ks < 4; ++ks) {
                    const int kb = ks * 8;
                    const int ar = wm * 16 + gid;
                    const int ac = kb + tig;
                    const uint32_t a0 = As[ar * AS_STRIDE + ac];
                    const uint32_t a1 = As[(ar + 8) * AS_STRIDE + ac];
                    const uint32_t a2 = As[ar * AS_STRIDE + ac + 4];
                    const uint32_t a3 = As[(ar + 8) * AS_STRIDE + ac + 4];
#pragma unroll
                    for (int nf = 0; nf < 8; ++nf) {
                        const int bn = wn * 64 + nf * 8 + gid;
                        const uint32_t b0 = Ws[(kb + tig) * WS_STRIDE + bn];
                        const uint32_t b1 = Ws[(kb + tig + 4) * WS_STRIDE + bn];
                        mma_tf32(acc[nf], a0, a1, a2, a3, b0, b1);
                    }
                }
                __syncthreads();
            }

            // ---- epilogue: bias, local (64-col) max, exp -> fp16 SMEM, local sum ----
            const int r0c = wm * 16 + gid;       // row of acc[.][0..1]
            const int r1c = r0c + 8;             // row of acc[.][2..3]
            float m0 = -3.4e38f, m1 = -3.4e38f;
#pragma unroll
            for (int nf = 0; nf < 8; ++nf) {
                const int col = n0 + wn * 64 + nf * 8 + tig * 2;
                const float bi0 = __ldg(bias + e * UDIM + col);
                const float bi1 = __ldg(bias + e * UDIM + col + 1);
                acc[nf][0] += bi0; acc[nf][1] += bi1;
                acc[nf][2] += bi0; acc[nf][3] += bi1;
                m0 = fmaxf(m0, fmaxf(acc[nf][0], acc[nf][1]));
                m1 = fmaxf(m1, fmaxf(acc[nf][2], acc[nf][3]));
            }
            // reduce max over the 4-lane quad (tig)
            m0 = fmaxf(m0, __shfl_xor_sync(0xffffffffu, m0, 1));
            m0 = fmaxf(m0, __shfl_xor_sync(0xffffffffu, m0, 2));
            m1 = fmaxf(m1, __shfl_xor_sync(0xffffffffu, m1, 1));
            m1 = fmaxf(m1, __shfl_xor_sync(0xffffffffu, m1, 2));

            float s0 = 0.f, s1 = 0.f;
#pragma unroll
            for (int nf = 0; nf < 8; ++nf) {
                const int col = n0 + wn * 64 + nf * 8 + tig * 2;
                const float e00 = __expf(acc[nf][0] - m0);
                const float e01 = __expf(acc[nf][1] - m0);
                const float e10 = __expf(acc[nf][2] - m1);
                const float e11 = __expf(acc[nf][3] - m1);
                s0 += e00 + e01;
                s1 += e10 + e11;
                ebuf[r0c * EB_STRIDE + (col >> 1)] = __floats2half2_rn(e00, e01);
                ebuf[r1c * EB_STRIDE + (col >> 1)] = __floats2half2_rn(e10, e11);
            }
            s0 += __shfl_xor_sync(0xffffffffu, s0, 1);
            s0 += __shfl_xor_sync(0xffffffffu, s0, 2);
            s1 += __shfl_xor_sync(0xffffffffu, s1, 1);
            s1 += __shfl_xor_sync(0xffffffffu, s1, 2);

            if (tig == 0) {
                const int sidx = (n0 >> 6) + wn;  // 64-col section index 0..15
                lmax[r0c * NSEC + sidx] = m0; lsum[r0c * NSEC + sidx] = s0;
                lmax[r1c * NSEC + sidx] = m1; lsum[r1c * NSEC + sidx] = s1;
            }
        }
        __syncthreads();

        // ---- combine: per-row log-sum-exp merge + weighted accumulate into out ----
        // 16 warps x 4 rows
#pragma unroll 1
        for (int rr = 0; rr < 4; ++rr) {
            const int r = (warp << 2) + rr;
            const float lm_l = (lane < NSEC) ? lmax[r * NSEC + lane] : -3.4e38f;
            float mf = lm_l;
#pragma unroll
            for (int o = 16; o > 0; o >>= 1)
                mf = fmaxf(mf, __shfl_xor_sync(0xffffffffu, mf, o));
            const float fj = (lane < NSEC) ? __expf(lm_l - mf) : 0.f;  // section factor
            float sf = (lane < NSEC) ? lsum[r * NSEC + lane] * fj : 0.f;
#pragma unroll
            for (int o = 16; o > 0; o >>= 1)
                sf += __shfl_xor_sync(0xffffffffu, sf, o);

            const float scale = __ldg(TP + (size_t)(row0 + r) * EDIM + e) / sf;
            const __half2* erow = ebuf + r * EB_STRIDE;
            float2* orow = reinterpret_cast<float2*>(out + (size_t)(row0 + r) * UDIM);

            if (e == 0) {
#pragma unroll
                for (int j = 0; j < 16; ++j) {
                    const float fac = scale * __shfl_sync(0xffffffffu, fj, j);
                    const float2 ef = __half22float2(erow[lane + 32 * j]);
                    float2 o2; o2.x = fac * ef.x; o2.y = fac * ef.y;
                    orow[lane + 32 * j] = o2;
                }
            } else {
#pragma unroll
                for (int j = 0; j < 16; ++j) {
                    const float fac = scale * __shfl_sync(0xffffffffu, fj, j);
                    const float2 ef = __half22float2(erow[lane + 32 * j]);
                    float2 o2 = orow[lane + 32 * j];
                    o2.x += fac * ef.x; o2.y += fac * ef.y;
                    orow[lane + 32 * j] = o2;
                }
            }
        }
        __syncthreads();
    }
}

extern "C" void kernel_launch(void* const* d_in, const int* in_sizes, int n_in,
                              void* d_out, int out_size) {
    // Identify inputs by element count (all distinct):
    // inputs 8192*1024=8388608, type_prob 8192*16=131072, W 16*1024*1024=16777216, b 16*1024=16384
    const float* X = nullptr;
    const float* TP = nullptr;
    const float* W = nullptr;
    const float* bias = nullptr;
    for (int i = 0; i < n_in; ++i) {
        switch (in_sizes[i]) {
            case 8388608:  X    = (const float*)d_in[i]; break;
            case 131072:   TP   = (const float*)d_in[i]; break;
            case 16777216: W    = (const float*)d_in[i]; break;
            case 16384:    bias = (const float*)d_in[i]; break;
            default: break;
        }
    }

    const size_t smem_bytes = (size_t)SMEM_FLOATS * sizeof(float);  // 183296
    cudaFuncSetAttribute(fused_proj_softmax_kernel,
                         cudaFuncAttributeMaxDynamicSharedMemorySize, (int)smem_bytes);

    fused_proj_softmax_kernel<<<BDIM / BM, NTHREADS, smem_bytes>>>(
        X, TP, W, bias, (float*)d_out);
}